// round 6
// baseline (speedup 1.0000x reference)
#include <cuda_runtime.h>

#define C_S 384
#define C_Z 128
#define MAX_N 2048
#define NSM 148
#define BLKS_PER_SM 8

// scratch for per-row projections (allocation-free rule: device globals)
__device__ float g_si[MAX_N];
__device__ float g_sj[MAX_N];
// sync state — always returned to 0 by the last exiting block, so every
// graph replay starts from the same state.
__device__ volatile unsigned g_ready;  // rows of si/sj published
__device__ unsigned g_exit;            // blocks exited

// ---------------------------------------------------------------------------
// Fused persistent kernel.
// Phase A (warps 0..N-1): si[n]/sj[n] row projections, publish with fence+count.
// Phase B (all warps): grid-stride over batches of 8 output rows (4 KB of z),
// software-pipelined double buffer so LDG.128s stay outstanding through the
// shfl-reduction tail. First z-load batch is issued BEFORE the spin-wait, so
// the precompute hides under the DRAM ramp.
// ---------------------------------------------------------------------------
__device__ __forceinline__ void load_batch(const float4* __restrict__ z4,
                                           long long batch, int lane,
                                           float4 v[8]) {
    size_t row0 = (size_t)batch * 8 * (C_Z / 4);
#pragma unroll
    for (int i = 0; i < 8; i++)
        v[i] = __ldg(z4 + row0 + (size_t)i * (C_Z / 4) + lane);
}

__device__ __forceinline__ void process_batch(const float4 v[8], float4 wz,
                                              float b0, long long batch,
                                              int lane, int N,
                                              float* __restrict__ out) {
    float a0 = v[0].x * wz.x + v[0].y * wz.y + v[0].z * wz.z + v[0].w * wz.w;
    float a1 = v[1].x * wz.x + v[1].y * wz.y + v[1].z * wz.z + v[1].w * wz.w;
    float a2 = v[2].x * wz.x + v[2].y * wz.y + v[2].z * wz.z + v[2].w * wz.w;
    float a3 = v[3].x * wz.x + v[3].y * wz.y + v[3].z * wz.z + v[3].w * wz.w;
    float a4 = v[4].x * wz.x + v[4].y * wz.y + v[4].z * wz.z + v[4].w * wz.w;
    float a5 = v[5].x * wz.x + v[5].y * wz.y + v[5].z * wz.z + v[5].w * wz.w;
    float a6 = v[6].x * wz.x + v[6].y * wz.y + v[6].z * wz.z + v[6].w * wz.w;
    float a7 = v[7].x * wz.x + v[7].y * wz.y + v[7].z * wz.z + v[7].w * wz.w;

    // Select-and-exchange multi-value reduction (9 shfls total).
    bool s0b = (lane & 1);
    float t0 = s0b ? a1 : a0;
    float t1 = s0b ? a3 : a2;
    float t2 = s0b ? a5 : a4;
    float t3 = s0b ? a7 : a6;
    t0 += __shfl_xor_sync(0xFFFFFFFFu, s0b ? a0 : a1, 1);
    t1 += __shfl_xor_sync(0xFFFFFFFFu, s0b ? a2 : a3, 1);
    t2 += __shfl_xor_sync(0xFFFFFFFFu, s0b ? a4 : a5, 1);
    t3 += __shfl_xor_sync(0xFFFFFFFFu, s0b ? a6 : a7, 1);
    bool s1b = (lane & 2);
    float u0 = s1b ? t1 : t0;
    float u1 = s1b ? t3 : t2;
    u0 += __shfl_xor_sync(0xFFFFFFFFu, s1b ? t0 : t1, 2);
    u1 += __shfl_xor_sync(0xFFFFFFFFu, s1b ? t2 : t3, 2);
    bool s2b = (lane & 4);
    float r = s2b ? u1 : u0;
    r += __shfl_xor_sync(0xFFFFFFFFu, s2b ? u0 : u1, 4);
    r += __shfl_xor_sync(0xFFFFFFFFu, r, 8);
    r += __shfl_xor_sync(0xFFFFFFFFu, r, 16);
    // lane l holds full sum for row (l & 7)

    if (lane < 8) {
        long long base = batch * 8;
        int n  = (int)(base / N);
        int m0 = (int)(base - (long long)n * N);
        out[base + lane] = r + g_si[n] + b0 + g_sj[m0 + lane];
    }
}

__global__ __launch_bounds__(256) void contact_fused_kernel(
    const float* __restrict__ s,
    const float* __restrict__ z,
    const float* __restrict__ W,
    const float* __restrict__ bias,
    float* __restrict__ out,
    int N) {
    int gwarp = (blockIdx.x * blockDim.x + threadIdx.x) >> 5;
    int lane  = threadIdx.x & 31;
    long long stride = (long long)(gridDim.x * blockDim.x) >> 5;  // total warps

    // ---- Phase A: si/sj precompute (warps 0..N-1, one row each) ----
    if (gwarp < N) {
        const float* srow = s + (size_t)gwarp * C_S;
        float ai = 0.f, aj = 0.f;
#pragma unroll
        for (int k = lane; k < C_S; k += 32) {
            float v = __ldg(srow + k);
            ai += v * __ldg(W + k);
            aj += v * __ldg(W + C_S + k);
        }
#pragma unroll
        for (int off = 16; off; off >>= 1) {
            ai += __shfl_xor_sync(0xFFFFFFFFu, ai, off);
            aj += __shfl_xor_sync(0xFFFFFFFFu, aj, off);
        }
        if (lane == 0) {
            g_si[gwarp] = ai;
            g_sj[gwarp] = aj;
            __threadfence();
            atomicAdd((unsigned*)&g_ready, 1u);
        }
    }

    // ---- Phase B: main stream ----
    long long nb = ((long long)N * N) / 8;  // total batches
    long long batch = gwarp;

    const float4* wz4 = (const float4*)(W + 2 * C_S);
    float4 wz = __ldg(wz4 + lane);
    float b0  = __ldg(bias);
    const float4* z4 = (const float4*)z;

    float4 va[8], vb[8];
    bool have = (batch < nb);
    if (have) load_batch(z4, batch, lane, va);  // issue loads BEFORE the wait

    // Wait for all si/sj rows (loads above are already in flight).
    if (lane == 0) {
        while (g_ready < (unsigned)N) { /* spin */ }
    }
    __syncwarp();
    __threadfence();  // acquire: order g_si/g_sj reads after the flag

    if (have) {
        for (;;) {
            long long nxt = batch + stride;
            if (nxt < nb) {
                load_batch(z4, nxt, lane, vb);
                process_batch(va, wz, b0, batch, lane, N, out);
                batch = nxt;
                long long nxt2 = batch + stride;
                if (nxt2 < nb) {
                    load_batch(z4, nxt2, lane, va);
                    process_batch(vb, wz, b0, batch, lane, N, out);
                    batch = nxt2;
                } else {
                    process_batch(vb, wz, b0, batch, lane, N, out);
                    break;
                }
            } else {
                process_batch(va, wz, b0, batch, lane, N, out);
                break;
            }
        }
    }

    // ---- Reset sync state: last block out restores zeros for next replay ----
    __syncthreads();
    if (threadIdx.x == 0) {
        unsigned done = atomicAdd(&g_exit, 1u);
        if (done == gridDim.x - 1) {
            g_exit = 0;
            *(unsigned*)&g_ready = 0;
            __threadfence();
        }
    }
}

extern "C" void kernel_launch(void* const* d_in, const int* in_sizes, int n_in,
                              void* d_out, int out_size) {
    const float* s    = (const float*)d_in[0];   // (1, N, 384)
    const float* z    = (const float*)d_in[1];   // (1, N, N, 128)
    const float* W    = (const float*)d_in[2];   // (1, 896)
    const float* bias = (const float*)d_in[3];   // (1,)
    float* out = (float*)d_out;                  // (1, N, N, 1)

    int N = in_sizes[0] / C_S;                   // B=1

    int threads = 256;
    int blocks = NSM * BLKS_PER_SM;  // grid-stride: correct for any residency
    contact_fused_kernel<<<blocks, threads>>>(s, z, W, bias, out, N);
}

// round 7
// speedup vs baseline: 1.1004x; 1.1004x over previous
#include <cuda_runtime.h>

#define C_S 384
#define C_Z 128
#define MAX_N 2048
#define NSM 148
#define MAIN_BLKS_PER_SM 3   // 72 regs x 256 thr -> 3 resident blocks/SM

// scratch for per-row projections (allocation-free rule: device globals)
__device__ float g_si[MAX_N];
__device__ float g_sj[MAX_N];

// ---------------------------------------------------------------------------
// Kernel 1: si[n] = dot(s[n,:], W[0:384]), sj[n] = dot(s[n,:], W[384:768])
// One warp per row, float4-vectorized: each lane does 3x LDG.128 of s and
// 6 broadcast float4 loads of W (L1-resident after first warp).
// ---------------------------------------------------------------------------
__global__ void precompute_sisj_kernel(const float* __restrict__ s,
                                       const float* __restrict__ W,
                                       int N) {
    int warp = (blockIdx.x * blockDim.x + threadIdx.x) >> 5;
    int lane = threadIdx.x & 31;
    if (warp >= N) return;
    const float4* s4  = (const float4*)(s + (size_t)warp * C_S);  // 96 float4
    const float4* wi4 = (const float4*)W;
    const float4* wj4 = (const float4*)(W + C_S);
    float ai = 0.f, aj = 0.f;
#pragma unroll
    for (int i = 0; i < 3; i++) {
        int k = lane + 32 * i;
        float4 v  = __ldg(s4 + k);
        float4 wi = __ldg(wi4 + k);
        float4 wj = __ldg(wj4 + k);
        ai += v.x * wi.x + v.y * wi.y + v.z * wi.z + v.w * wi.w;
        aj += v.x * wj.x + v.y * wj.y + v.z * wj.z + v.w * wj.w;
    }
#pragma unroll
    for (int off = 16; off; off >>= 1) {
        ai += __shfl_xor_sync(0xFFFFFFFFu, ai, off);
        aj += __shfl_xor_sync(0xFFFFFFFFu, aj, off);
    }
    if (lane == 0) {
        g_si[warp] = ai;
        g_sj[warp] = aj;
    }
}

// ---------------------------------------------------------------------------
// Kernel 2: persistent warps (one wave), software-pipelined double buffer.
// Each batch = 8 consecutive output rows m (4 KB of z). A warp issues the
// NEXT batch's 8x LDG.128 before reducing the CURRENT batch, keeping DRAM
// loads outstanding through the shfl-reduction tail.
// ---------------------------------------------------------------------------
__device__ __forceinline__ void load_batch(const float4* __restrict__ z4,
                                           long long batch, int lane,
                                           float4 v[8]) {
    size_t row0 = (size_t)batch * 8 * (C_Z / 4);
#pragma unroll
    for (int i = 0; i < 8; i++)
        v[i] = __ldg(z4 + row0 + (size_t)i * (C_Z / 4) + lane);
}

__device__ __forceinline__ void process_batch(const float4 v[8], float4 wz,
                                              float b0, long long batch,
                                              int lane, int N,
                                              float* __restrict__ out) {
    float a0 = v[0].x * wz.x + v[0].y * wz.y + v[0].z * wz.z + v[0].w * wz.w;
    float a1 = v[1].x * wz.x + v[1].y * wz.y + v[1].z * wz.z + v[1].w * wz.w;
    float a2 = v[2].x * wz.x + v[2].y * wz.y + v[2].z * wz.z + v[2].w * wz.w;
    float a3 = v[3].x * wz.x + v[3].y * wz.y + v[3].z * wz.z + v[3].w * wz.w;
    float a4 = v[4].x * wz.x + v[4].y * wz.y + v[4].z * wz.z + v[4].w * wz.w;
    float a5 = v[5].x * wz.x + v[5].y * wz.y + v[5].z * wz.z + v[5].w * wz.w;
    float a6 = v[6].x * wz.x + v[6].y * wz.y + v[6].z * wz.z + v[6].w * wz.w;
    float a7 = v[7].x * wz.x + v[7].y * wz.y + v[7].z * wz.z + v[7].w * wz.w;

    // Select-and-exchange multi-value reduction (9 shfls total).
    bool s0b = (lane & 1);
    float t0 = s0b ? a1 : a0;
    float t1 = s0b ? a3 : a2;
    float t2 = s0b ? a5 : a4;
    float t3 = s0b ? a7 : a6;
    t0 += __shfl_xor_sync(0xFFFFFFFFu, s0b ? a0 : a1, 1);
    t1 += __shfl_xor_sync(0xFFFFFFFFu, s0b ? a2 : a3, 1);
    t2 += __shfl_xor_sync(0xFFFFFFFFu, s0b ? a4 : a5, 1);
    t3 += __shfl_xor_sync(0xFFFFFFFFu, s0b ? a6 : a7, 1);
    bool s1b = (lane & 2);
    float u0 = s1b ? t1 : t0;
    float u1 = s1b ? t3 : t2;
    u0 += __shfl_xor_sync(0xFFFFFFFFu, s1b ? t0 : t1, 2);
    u1 += __shfl_xor_sync(0xFFFFFFFFu, s1b ? t2 : t3, 2);
    bool s2b = (lane & 4);
    float r = s2b ? u1 : u0;
    r += __shfl_xor_sync(0xFFFFFFFFu, s2b ? u0 : u1, 4);
    r += __shfl_xor_sync(0xFFFFFFFFu, r, 8);
    r += __shfl_xor_sync(0xFFFFFFFFu, r, 16);
    // lane l holds full sum for row (l & 7)

    if (lane < 8) {
        long long base = batch * 8;
        int n  = (int)(base / N);
        int m0 = (int)(base - (long long)n * N);
        out[base + lane] = r + g_si[n] + b0 + g_sj[m0 + lane];
    }
}

__global__ __launch_bounds__(256) void contact_main_kernel(
    const float* __restrict__ z,
    const float* __restrict__ W,
    const float* __restrict__ bias,
    float* __restrict__ out,
    int N) {
    int gwarp = (blockIdx.x * blockDim.x + threadIdx.x) >> 5;
    int lane  = threadIdx.x & 31;
    long long stride = (long long)(gridDim.x * blockDim.x) >> 5;  // total warps

    long long nb = ((long long)N * N) / 8;  // total batches
    long long batch = gwarp;
    if (batch >= nb) return;

    const float4* wz4 = (const float4*)(W + 2 * C_S);
    float4 wz = __ldg(wz4 + lane);
    float b0  = __ldg(bias);
    const float4* z4 = (const float4*)z;

    float4 va[8], vb[8];
    load_batch(z4, batch, lane, va);

    for (;;) {
        long long nxt = batch + stride;
        if (nxt < nb) {
            load_batch(z4, nxt, lane, vb);                  // loads in flight...
            process_batch(va, wz, b0, batch, lane, N, out); // ...through tail
            batch = nxt;
            long long nxt2 = batch + stride;
            if (nxt2 < nb) {
                load_batch(z4, nxt2, lane, va);
                process_batch(vb, wz, b0, batch, lane, N, out);
                batch = nxt2;
            } else {
                process_batch(vb, wz, b0, batch, lane, N, out);
                break;
            }
        } else {
            process_batch(va, wz, b0, batch, lane, N, out);
            break;
        }
    }
}

extern "C" void kernel_launch(void* const* d_in, const int* in_sizes, int n_in,
                              void* d_out, int out_size) {
    const float* s    = (const float*)d_in[0];   // (1, N, 384)
    const float* z    = (const float*)d_in[1];   // (1, N, N, 128)
    const float* W    = (const float*)d_in[2];   // (1, 896)
    const float* bias = (const float*)d_in[3];   // (1,)
    float* out = (float*)d_out;                  // (1, N, N, 1)

    int N = in_sizes[0] / C_S;                   // B=1

    // Kernel 1: one warp per row
    {
        int warps = N;
        int threads = 256;
        int blocks = (warps * 32 + threads - 1) / threads;
        precompute_sisj_kernel<<<blocks, threads>>>(s, W, N);
    }

    // Kernel 2: one-wave persistent grid (3 blocks/SM at 72 regs)
    {
        int threads = 256;
        int blocks = NSM * MAIN_BLKS_PER_SM;
        contact_main_kernel<<<blocks, threads>>>(z, W, bias, out, N);
    }
}